// round 11
// baseline (speedup 1.0000x reference)
#include <cuda_runtime.h>

#define POOL 14
#define H 128
#define W 128
#define C 1024
#define R 256
#define C4 (C / 4)

// R11 = R10 resubmission (previous round failed with "device busy" at
// harness init — infra error, kernel never executed).
//
// Probe: R6 dataflow (best 53.3us) with fatter threads.
// 128 threads/CTA, each thread handles TWO float4 channel-groups
// (c4 and c4+128) -> 8 batched LDG.128 per px per thread (2x per-warp MLP).
// Bet: kernel is latency-limited (no pipe >70%); wins so far all came from
// more batched loads in flight, not more warps. Occupancy drops (~37%),
// in-flight bytes rise (~+40%).
// Everything else identical: x-tuple precompute in shared, zero-weight
// corner aliasing (bit-exact), full 14-px unroll, __stcs streaming stores.
__global__ __launch_bounds__(128) void roi_resize_kernel(
    const float4* __restrict__ img,   // [H, W, C4]
    const float*  __restrict__ rois,  // [R, 4]
    float4*       __restrict__ out)   // [R, POOL, POOL, C4]
{
    const int py = blockIdx.x;          // 0..13
    const int r  = blockIdx.y;          // 0..255
    const int ca = threadIdx.x;         // channel-group A: 0..127
    const int cb = ca + 128;            // channel-group B: 128..255

    __shared__ int   s_ax0[POOL];
    __shared__ int   s_ax1[POOL];
    __shared__ float s_fx [POOL];

    const int x1 = (int)rois[r * 4 + 0];
    const int y1 = (int)rois[r * 4 + 1];
    const int x2 = (int)rois[r * 4 + 2];
    const int y2 = (int)rois[r * 4 + 3];

    if (threadIdx.x < POOL) {
        const float ww = (float)(x2 - x1);
        const float src_x = (float)threadIdx.x * (ww * (1.0f / POOL));
        const int   x0 = (int)floorf(src_x);
        const int   x1i = min(x0 + 1, (x2 - x1) - 1);
        const float fx = src_x - (float)x0;
        const int   ax0 = min(max(x1 + x0, 0), W - 1);
        int         ax1 = min(max(x1 + x1i, 0), W - 1);
        if (fx == 0.0f) ax1 = ax0;      // zero-weight corner -> alias address
        s_fx [threadIdx.x] = fx;
        s_ax0[threadIdx.x] = ax0;
        s_ax1[threadIdx.x] = ax1;
    }

    const float hh = (float)(y2 - y1);
    const float src_y = (float)py * (hh * (1.0f / POOL));
    const int   y0 = (int)floorf(src_y);
    const float fy = src_y - (float)y0;
    const int   y1i = min(y0 + 1, (y2 - y1) - 1);
    const int   ay0 = min(max(y1 + y0, 0), H - 1);
    int         ay1 = min(max(y1 + y1i, 0), H - 1);
    if (fy == 0.0f) ay1 = ay0;          // zero-weight row -> alias address

    __syncthreads();

    const float4* __restrict__ r0a = img + (size_t)(ay0 * W) * C4 + ca;
    const float4* __restrict__ r1a = img + (size_t)(ay1 * W) * C4 + ca;
    const float4* __restrict__ r0b = img + (size_t)(ay0 * W) * C4 + cb;
    const float4* __restrict__ r1b = img + (size_t)(ay1 * W) * C4 + cb;
    float4* __restrict__ orow = out + ((size_t)(r * POOL + py) * POOL) * C4;

    #pragma unroll
    for (int px = 0; px < POOL; px++) {
        const int   ax0 = s_ax0[px];
        const int   ax1 = s_ax1[px];
        const float fx  = s_fx[px];
        const int   o0  = ax0 * C4;
        const int   o1  = ax1 * C4;

        // 8 independent loads — doubled per-warp MLP
        const float4 a00 = r0a[o0];
        const float4 a01 = r0a[o1];
        const float4 a10 = r1a[o0];
        const float4 a11 = r1a[o1];
        const float4 b00 = r0b[o0];
        const float4 b01 = r0b[o1];
        const float4 b10 = r1b[o0];
        const float4 b11 = r1b[o1];

        float4 oa, ob;
        {
            float top = a00.x + (a01.x - a00.x) * fx;
            float bot = a10.x + (a11.x - a10.x) * fx;
            oa.x = top + (bot - top) * fy;
        }
        {
            float top = a00.y + (a01.y - a00.y) * fx;
            float bot = a10.y + (a11.y - a10.y) * fx;
            oa.y = top + (bot - top) * fy;
        }
        {
            float top = a00.z + (a01.z - a00.z) * fx;
            float bot = a10.z + (a11.z - a10.z) * fx;
            oa.z = top + (bot - top) * fy;
        }
        {
            float top = a00.w + (a01.w - a00.w) * fx;
            float bot = a10.w + (a11.w - a10.w) * fx;
            oa.w = top + (bot - top) * fy;
        }
        {
            float top = b00.x + (b01.x - b00.x) * fx;
            float bot = b10.x + (b11.x - b10.x) * fx;
            ob.x = top + (bot - top) * fy;
        }
        {
            float top = b00.y + (b01.y - b00.y) * fx;
            float bot = b10.y + (b11.y - b10.y) * fx;
            ob.y = top + (bot - top) * fy;
        }
        {
            float top = b00.z + (b01.z - b00.z) * fx;
            float bot = b10.z + (b11.z - b10.z) * fx;
            ob.z = top + (bot - top) * fy;
        }
        {
            float top = b00.w + (b01.w - b00.w) * fx;
            float bot = b10.w + (b11.w - b10.w) * fx;
            ob.w = top + (bot - top) * fy;
        }

        __stcs(&orow[(size_t)px * C4 + ca], oa);
        __stcs(&orow[(size_t)px * C4 + cb], ob);
    }
}

extern "C" void kernel_launch(void* const* d_in, const int* in_sizes, int n_in,
                              void* d_out, int out_size) {
    const float4* img  = (const float4*)d_in[0];
    const float*  rois = (const float*)d_in[1];
    float4*       out  = (float4*)d_out;

    dim3 grid(POOL, R);
    roi_resize_kernel<<<grid, 128>>>(img, rois, out);
}

// round 12
// speedup vs baseline: 1.0758x; 1.0758x over previous
#include <cuda_runtime.h>

#define POOL 14
#define H 128
#define W 128
#define C 1024
#define R 256
#define C4 (C / 4)

// FINAL — R6 configuration (best measured 53.3us; reproduced 53.98us).
//
// One CTA per (roi, py) output row; 256 threads = one float4 channel-group
// each. x-side gather tuples precomputed by threads 0..13 into shared;
// y-side scalars once per CTA. Full 14-px unroll lets ptxas front-batch
// the 4 straight LDG.128 per px (48 regs is load-bearing). Streaming
// __stcs keeps the 64MB img L2-resident (DRAM traffic is ~95% compulsory
// output writes, ~4.0-4.2TB/s pure-write rate). Zero-weight corners
// (fx==0 / fy==0, ~26% each) are aliased to the already-loaded address in
// the precompute — bit-exact, converts those reads into L1 hits at zero
// inner-loop instruction cost.
//
// Measured dead ends (do not reintroduce):
//   sw-pipelining (R3 +6us), reg caps 40/42 (R3/R7 up to +33us),
//   per-px predicated load skips (R4 +4us), uniform two-path bodies
//   (R5 +25us), __stwt write-through (R8 +4us), 128-thr fat threads
//   with 2 channel-groups (R11 +4.8us).
__global__ __launch_bounds__(256) void roi_resize_kernel(
    const float4* __restrict__ img,   // [H, W, C4]
    const float*  __restrict__ rois,  // [R, 4]
    float4*       __restrict__ out)   // [R, POOL, POOL, C4]
{
    const int py = blockIdx.x;          // 0..13
    const int r  = blockIdx.y;          // 0..255
    const int c4 = threadIdx.x;         // 0..255

    __shared__ int   s_ax0[POOL];
    __shared__ int   s_ax1[POOL];
    __shared__ float s_fx [POOL];

    const int x1 = (int)rois[r * 4 + 0];
    const int y1 = (int)rois[r * 4 + 1];
    const int x2 = (int)rois[r * 4 + 2];
    const int y2 = (int)rois[r * 4 + 3];

    if (threadIdx.x < POOL) {
        const float ww = (float)(x2 - x1);
        const float src_x = (float)threadIdx.x * (ww * (1.0f / POOL));
        const int   x0 = (int)floorf(src_x);
        const int   x1i = min(x0 + 1, (x2 - x1) - 1);
        const float fx = src_x - (float)x0;
        const int   ax0 = min(max(x1 + x0, 0), W - 1);
        int         ax1 = min(max(x1 + x1i, 0), W - 1);
        if (fx == 0.0f) ax1 = ax0;      // zero-weight corner -> alias address
        s_fx [threadIdx.x] = fx;
        s_ax0[threadIdx.x] = ax0;
        s_ax1[threadIdx.x] = ax1;
    }

    const float hh = (float)(y2 - y1);
    const float src_y = (float)py * (hh * (1.0f / POOL));
    const int   y0 = (int)floorf(src_y);
    const float fy = src_y - (float)y0;
    const int   y1i = min(y0 + 1, (y2 - y1) - 1);
    const int   ay0 = min(max(y1 + y0, 0), H - 1);
    int         ay1 = min(max(y1 + y1i, 0), H - 1);
    if (fy == 0.0f) ay1 = ay0;          // zero-weight row -> alias address

    __syncthreads();

    const float4* __restrict__ row0 = img + (size_t)(ay0 * W) * C4 + c4;
    const float4* __restrict__ row1 = img + (size_t)(ay1 * W) * C4 + c4;
    float4* __restrict__ orow = out + ((size_t)(r * POOL + py) * POOL) * C4 + c4;

    #pragma unroll
    for (int px = 0; px < POOL; px++) {
        const int   ax0 = s_ax0[px];
        const int   ax1 = s_ax1[px];
        const float fx  = s_fx[px];

        const float4 v00 = row0[ax0 * C4];
        const float4 v01 = row0[ax1 * C4];
        const float4 v10 = row1[ax0 * C4];
        const float4 v11 = row1[ax1 * C4];

        float4 o;
        {
            float top = v00.x + (v01.x - v00.x) * fx;
            float bot = v10.x + (v11.x - v10.x) * fx;
            o.x = top + (bot - top) * fy;
        }
        {
            float top = v00.y + (v01.y - v00.y) * fx;
            float bot = v10.y + (v11.y - v10.y) * fx;
            o.y = top + (bot - top) * fy;
        }
        {
            float top = v00.z + (v01.z - v00.z) * fx;
            float bot = v10.z + (v11.z - v10.z) * fx;
            o.z = top + (bot - top) * fy;
        }
        {
            float top = v00.w + (v01.w - v00.w) * fx;
            float bot = v10.w + (v11.w - v10.w) * fx;
            o.w = top + (bot - top) * fy;
        }

        __stcs(&orow[(size_t)px * C4], o);   // evict-first streaming store
    }
}

extern "C" void kernel_launch(void* const* d_in, const int* in_sizes, int n_in,
                              void* d_out, int out_size) {
    const float4* img  = (const float4*)d_in[0];
    const float*  rois = (const float*)d_in[1];
    float4*       out  = (float4*)d_out;

    dim3 grid(POOL, R);
    roi_resize_kernel<<<grid, 256>>>(img, rois, out);
}